// round 15
// baseline (speedup 1.0000x reference)
#include <cuda_runtime.h>
#include <math.h>

#define NB 128
#define NN 4096
#define KK 15
#define EPSV 0.1f
#define SMALLV 1e-20f
#define MUV 2.44140625e-4f   /* 1/4096 */
#define NU0 (4081.0f/4096.0f)
#define NITER 200
#define CONVTOL 1e-6f
#define LOG2E 1.4426950408889634f

typedef unsigned long long ull;

// ---------------- device scratch (static, no allocation) ----------------
__device__ float g_sig[NB * KK * NN];   // sigmoid+SMALL, layout [b][j][i]
__device__ float g_colsum[NB * KK];     // per-(b,j) column sums of sig (atomic)
__device__ float g_tv[NB * KK];         // top-15 values per row (descending)
__device__ float g_y[NB * 5];           // partial y_r (atomic)
__device__ float g_cb[NB * KK];         // partial colsum of b (atomic)
__device__ float g_w[NB * 16];          // final Sinkhorn state (kMain -> kOut)
__device__ float g_w1s[5];              // sum over i<N of w1[i,r]
__device__ float g_mx[128], g_mn[128];
__device__ int   g_fl[128];
__device__ double g_norm;
__device__ unsigned g_cnt0;             // kPre0 completion counter (self-reset)
__device__ unsigned g_cnt;              // kOut completion counter (self-reset)

struct Par { float filled, invCmax, alpha, inv_tau, c_exp2, itau2, capAbs, epsitau; };
__device__ Par g_P;

// ---------------- helpers ----------------
__device__ __forceinline__ float warp_sum(float v) {
#pragma unroll
    for (int o = 16; o > 0; o >>= 1) v += __shfl_xor_sync(0xffffffffu, v, o);
    return v;
}
__device__ __forceinline__ float warp_max(float v) {
#pragma unroll
    for (int o = 16; o > 0; o >>= 1) v = fmaxf(v, __shfl_xor_sync(0xffffffffu, v, o));
    return v;
}
__device__ __forceinline__ float warp_min(float v) {
#pragma unroll
    for (int o = 16; o > 0; o >>= 1) v = fminf(v, __shfl_xor_sync(0xffffffffu, v, o));
    return v;
}
__device__ __forceinline__ int warp_or(int v) {
#pragma unroll
    for (int o = 16; o > 0; o >>= 1) v |= __shfl_xor_sync(0xffffffffu, v, o);
    return v;
}
__device__ __forceinline__ float rcpa(float x) {
    float y; asm("rcp.approx.f32 %0, %1;" : "=f"(y) : "f"(x)); return y;
}
__device__ __forceinline__ float fixs(float s) {
    return (isinf(s) && s < 0.0f) ? g_P.filled : s;
}
// sentinel variant for kPre0's top-15 (runs before g_P exists)
__device__ __forceinline__ float fixinf(float s) {
    return (isinf(s) && s < 0.0f) ? -3.4e38f : s;
}

// ---------------- packed f32x2 (sm_103a) ----------------
__device__ __forceinline__ ull pk2(float lo, float hi) {
    ull r; asm("mov.b64 %0, {%1,%2};" : "=l"(r) : "f"(lo), "f"(hi)); return r;
}
__device__ __forceinline__ void upk2(float& lo, float& hi, ull v) {
    asm("mov.b64 {%0,%1}, %2;" : "=f"(lo), "=f"(hi) : "l"(v));
}
__device__ __forceinline__ ull fma2(ull a, ull b, ull c) {
    ull d; asm("fma.rn.f32x2 %0, %1, %2, %3;" : "=l"(d) : "l"(a), "l"(b), "l"(c)); return d;
}
__device__ __forceinline__ ull mul2(ull a, ull b) {
    ull d; asm("mul.rn.f32x2 %0, %1, %2;" : "=l"(d) : "l"(a), "l"(b)); return d;
}
__device__ __forceinline__ ull add2(ull a, ull b) {
    ull d; asm("add.rn.f32x2 %0, %1, %2;" : "=l"(d) : "l"(a), "l"(b)); return d;
}

// ---------------- fused prepass 0: top-15 (blocks<NB) + minmax (blocks>=NB)
//                  + last-block param finalize + W1sum + accumulator zeroing ----
__global__ __launch_bounds__(512) void kPre0(const float* __restrict__ scores,
                                             const float* __restrict__ tau,
                                             const float* __restrict__ w1) {
    int blk = blockIdx.x, tid = threadIdx.x, lane = tid & 31, wid = tid >> 5;
    __shared__ float swm[16];
    __shared__ float sbc;
    __shared__ int claim;
    __shared__ float smx[16], smn[16]; __shared__ int sfl[16];
    __shared__ unsigned stkt;
    __shared__ float sws[16][5];

    if (blk < NB) {
        // ---- top-15 for row blk via 15 masked argmax rounds ----
        const float4* p4 = reinterpret_cast<const float4*>(scores + blk * NN) + tid * 2;
        float4 a = p4[0], c4 = p4[1];
        float v[8] = {a.x, a.y, a.z, a.w, c4.x, c4.y, c4.z, c4.w};
#pragma unroll
        for (int e = 0; e < 8; e++) v[e] = fixinf(v[e]);
        for (int r = 0; r < KK; r++) {
            float lm = v[0];
#pragma unroll
            for (int e = 1; e < 8; e++) lm = fmaxf(lm, v[e]);
            lm = warp_max(lm);
            if (!lane) swm[wid] = lm;
            __syncthreads();
            if (tid == 0) {
                float m = swm[0];
                for (int w = 1; w < 16; w++) m = fmaxf(m, swm[w]);
                sbc = m; claim = 0;
                g_tv[blk * KK + r] = m;
            }
            __syncthreads();
            float m = sbc;
            int idx = -1;
#pragma unroll
            for (int e = 0; e < 8; e++) if (idx < 0 && v[e] == m) idx = e;
            if (idx >= 0) {
                int old = atomicAdd(&claim, 1);
                if (old == 0) v[idx] = -3.4e38f;
            }
        }
    } else {
        int mb = blk - NB;   // 0..127
        if (mb == 0) {
            for (int i = tid; i < NB * KK; i += 512) { g_colsum[i] = 0.0f; g_cb[i] = 0.0f; }
            for (int i = tid; i < NB * 5; i += 512) g_y[i] = 0.0f;
            if (tid == 0) g_norm = 0.0;
        }
        // ---- minmax over slice [mb*4096, (mb+1)*4096) ----
        const float4* p4 = reinterpret_cast<const float4*>(scores + mb * 4096) + tid * 2;
        float4 a = p4[0], c4 = p4[1];
        float vs[8] = {a.x, a.y, a.z, a.w, c4.x, c4.y, c4.z, c4.w};
        float mx = -3.4e38f, mn = 3.4e38f; int fl = 0;
#pragma unroll
        for (int t = 0; t < 8; t++) {
            float x = vs[t];
            if (isinf(x) && x < 0.0f) fl = 1;
            else mn = fminf(mn, x);
            mx = fmaxf(mx, x);
        }
        mx = warp_max(mx); mn = warp_min(mn); fl = warp_or(fl);
        if (!lane) { smx[wid] = mx; smn[wid] = mn; sfl[wid] = fl; }
        __syncthreads();
        if (tid == 0) {
            for (int w = 1; w < 16; w++) { mx = fmaxf(mx, smx[w]); mn = fminf(mn, smn[w]); fl |= sfl[w]; }
            g_mx[mb] = mx; g_mn[mb] = mn; g_fl[mb] = fl;
        }
    }

    // ---- completion ticket; last block finalizes ----
    __syncthreads();
    if (tid == 0) { __threadfence(); stkt = atomicAdd(&g_cnt0, 1u); }
    __syncthreads();
    if (stkt == 2 * NB - 1) {
        float mx = (tid < 128) ? g_mx[tid] : -3.4e38f;
        float mn = (tid < 128) ? g_mn[tid] : 3.4e38f;
        int fl = (tid < 128) ? g_fl[tid] : 0;
        mx = warp_max(mx); mn = warp_min(mn); fl = warp_or(fl);
        if (!lane) { smx[wid] = mx; smn[wid] = mn; sfl[wid] = fl; }
        __syncthreads();
        if (tid == 0) {
            for (int w = 1; w < 4; w++) { mx = fmaxf(mx, smx[w]); mn = fminf(mn, smn[w]); fl |= sfl[w]; }
            float filled = mn - (mx - mn);
            float lo = fl ? filled : mn;
            float d1 = lo - 15.0f, d2 = mx - 15.0f;
            float Cmax = fmaxf(fmaxf(lo * lo, d1 * d1), fmaxf(mx * mx, d2 * d2));
            float invC = 1.0f / Cmax;
            Par P;
            P.filled = filled; P.invCmax = invC; P.alpha = 10.0f * invC;
            P.inv_tau = 1.0f / tau[0];
            P.c_exp2 = 2.0f * (10.0f * invC) * LOG2E;
            P.itau2 = P.inv_tau * LOG2E;
            P.capAbs = 46.0517362f / P.inv_tau;
            P.epsitau = EPSV * P.inv_tau;
            g_P = P;
        }
        // W1sum_r = sum_{i<N} w1[i*5+r]
        float acc[5] = {0, 0, 0, 0, 0};
        for (int i = tid; i < NN; i += 512) {
            const float* wr = w1 + (size_t)i * 5;
#pragma unroll
            for (int r = 0; r < 5; r++) acc[r] += wr[r];
        }
#pragma unroll
        for (int r = 0; r < 5; r++) acc[r] = warp_sum(acc[r]);
        if (!lane) {
#pragma unroll
            for (int r = 0; r < 5; r++) sws[wid][r] = acc[r];
        }
        __syncthreads();
        if (tid < 5) {
            float a = 0.0f;
            for (int w = 0; w < 16; w++) a += sws[w][tid];
            g_w1s[tid] = a;
        }
        if (tid == 0) g_cnt0 = 0;   // reset for next graph replay
    }
}

// ---------------- B: sigmoids + colsums, 8 CTAs per row ----------------
__global__ __launch_bounds__(256) void kB(const float* __restrict__ scores) {
    int blk = blockIdx.x;
    int b = blk >> 3, q = blk & 7;
    int tid = threadIdx.x, lane = tid & 31, wid = tid >> 5;
    __shared__ float sEj[KK], srEj[KK];
    float it2 = g_P.itau2;
    if (tid < KK) {
        float E = exp2f(g_tv[b * KK + tid] * it2);
        sEj[tid] = E;
        srEj[tid] = 1.0f / E;
    }
    __syncthreads();
    float cs[KK];
#pragma unroll
    for (int j = 0; j < KK; j++) cs[j] = 0.0f;
    for (int e = 0; e < 2; e++) {
        int i = q * 512 + e * 256 + tid;
        float s = fixs(scores[b * NN + i]);
        float E = exp2f(s * it2);
        float rE = rcpa(E);
#pragma unroll
        for (int j = 0; j < KK; j++) {
            float ed = fmaxf(sEj[j] * rE, E * srEj[j]);
            float sg = rcpa(1.0f + ed) + SMALLV;
            g_sig[(b * KK + j) * NN + i] = sg;
            cs[j] += sg;
        }
    }
#pragma unroll
    for (int j = 0; j < KK; j++) cs[j] = warp_sum(cs[j]);
    __shared__ float scs[8][KK];
    if (!lane) {
#pragma unroll
        for (int j = 0; j < KK; j++) scs[wid][j] = cs[j];
    }
    __syncthreads();
    if (tid < KK) {
        float a = 0.0f;
        for (int w = 0; w < 8; w++) a += scs[w][tid];
        atomicAdd(&g_colsum[b * KK + tid], a);
    }
}

// ---------------- C: warm-start partials (no logs except lnlast) ----------------
// ln(sig_c) ~= -min(|tv_c-s|,cap)/tau - sig_c  (first-order log1p correction)
// R_i = quad*invC - epsitau*rowA - EPS*rowSg + EPS*lnlast  (SL deferred to kMain)
// cb_c partial = quadcol*invC - epsitau*colA_c  (-EPS*colsum_c and -4096*lc_c in kMain)
__global__ __launch_bounds__(256) void kC(const float* __restrict__ scores,
                                          const float* __restrict__ w1) {
    int blk = blockIdx.x;
    int b = blk >> 3, q = blk & 7;
    int tid = threadIdx.x, lane = tid & 31, wid = tid >> 5;
    __shared__ float sinv[KK], stv[KK];
    if (tid < KK) {
        sinv[tid] = 1.0f / g_colsum[b * KK + tid];
        stv[tid] = g_tv[b * KK + tid];
    }
    __syncthreads();
    float invC = g_P.invCmax, capA = g_P.capAbs, epst = g_P.epsitau;
    float y[5] = {0, 0, 0, 0, 0};
    float colA[KK];
#pragma unroll
    for (int c = 0; c < KK; c++) colA[c] = 0.0f;
    float ssum = 0.0f, ssum2 = 0.0f;
    for (int e = 0; e < 2; e++) {
        int i = q * 512 + e * 256 + tid;
        float s = fixs(scores[b * NN + i]);
        float rowacc = 0.0f, rowA = 0.0f, rowSg = 0.0f;
#pragma unroll
        for (int c = 0; c < KK; c++) {
            float sg = g_sig[(b * KK + c) * NN + i];
            rowacc += sg * sinv[c];
            rowSg += sg;
            float ad = fminf(fabsf(stv[c] - s), capA);
            rowA += ad;
            colA[c] += ad;
        }
        ssum += s; ssum2 += s * s;
        float last = fminf(fmaxf((1.0f - rowacc) * MUV, SMALLV), 1.0f - SMALLV);
        float lnl = __logf(last);
        float R = (16.0f * s * s - 240.0f * s + 1240.0f) * invC
                - epst * rowA - EPSV * rowSg + EPSV * lnl;
        const float* wr = w1 + (size_t)i * 5;
#pragma unroll
        for (int r = 0; r < 5; r++) y[r] += R * wr[r];
    }
#pragma unroll
    for (int r = 0; r < 5; r++) y[r] = warp_sum(y[r]);
#pragma unroll
    for (int c = 0; c < KK; c++) colA[c] = warp_sum(colA[c]);
    ssum = warp_sum(ssum);
    ssum2 = warp_sum(ssum2);
    __shared__ float sy[8][5], scl[8][KK], sss[8], sss2[8];
    if (!lane) {
#pragma unroll
        for (int r = 0; r < 5; r++) sy[wid][r] = y[r];
#pragma unroll
        for (int c = 0; c < KK; c++) scl[wid][c] = colA[c];
        sss[wid] = ssum; sss2[wid] = ssum2;
    }
    __syncthreads();
    if (tid < 5) {
        float a = 0.0f;
        for (int w = 0; w < 8; w++) a += sy[w][tid];
        atomicAdd(&g_y[b * 5 + tid], a);
    }
    if (tid >= 32 && tid < 32 + KK) {
        int c = tid - 32;
        float ca = 0.0f, S1 = 0.0f, S2 = 0.0f;
        for (int w = 0; w < 8; w++) { ca += scl[w][c]; S1 += sss[w]; S2 += sss2[w]; }
        float a = (float)(KK - c);   // anchor for column c
        float cb = (S2 - 2.0f * a * S1 + 512.0f * a * a) * invC - epst * ca;
        atomicAdd(&g_cb[b * KK + c], cb);
    }
}

// ---------------- main: warm-start assembly + Sinkhorn loop (early exit) ----------------
__global__ __launch_bounds__(256) void kMain(const float* __restrict__ scores,
                                             const float* __restrict__ w1) {
    int b = blockIdx.x, tid = threadIdx.x, lane = tid & 31, wid = tid >> 5;  // 8 warps
    __shared__ float sS[2][8][16];
    __shared__ float lcs[KK];
    __shared__ float sSL;
    __shared__ float yf[5], ggs[KK], sWinit[16];
    float c2 = g_P.c_exp2;
    const float2* sc2 = reinterpret_cast<const float2*>(scores + b * NN);

    // assemble initial w from partial sums
    if (tid < KK) lcs[tid] = EPSV * __logf(4096.0f * g_colsum[b * KK + tid]);
    __syncthreads();
    if (tid == 0) {
        float a = 0.0f;
        for (int c = 0; c < KK; c++) a += lcs[c];
        sSL = a;
    }
    __syncthreads();
    if (tid < 5) {
        float a = g_y[b * 5 + tid] - sSL * g_w1s[tid];
        for (int c = 0; c < KK; c++) {
            float cbf = g_cb[b * KK + c] - 4096.0f * lcs[c] - EPSV * g_colsum[b * KK + c];
            a += cbf * w1[(size_t)(NN + c) * 5 + tid];
        }
        yf[tid] = a;
    }
    __syncthreads();
    if (tid < KK) {
        float g = 0.0f;
#pragma unroll
        for (int r = 0; r < 5; r++) g += yf[r] * w1[(size_t)(NN + tid) * 5 + r];
        ggs[tid] = g;
    }
    __syncthreads();
    if (tid < 16) {
        sWinit[tid] = (tid == 0) ? 1.0f
            : __expf(10.0f * ggs[KK - tid] - g_P.alpha * (float)(tid * tid));
    }

    ull X[8];
    ull P[8][7];
#pragma unroll
    for (int p = 0; p < 8; p++) {
        float2 s = sc2[tid + p * 256];
        float xlo = exp2f(c2 * fixs(s.x));
        float xhi = exp2f(c2 * fixs(s.y));
        ull x = pk2(xlo, xhi);
        X[p] = x;
        ull x2 = mul2(x, x);
        P[p][0] = x2;
#pragma unroll
        for (int j = 1; j < 7; j++) P[p][j] = mul2(P[p][j - 1], x2);
    }
    __syncthreads();
    ull W[16];
#pragma unroll
    for (int m = 0; m < 16; m++) { float v = sWinit[m]; W[m] = pk2(v, v); }
    float wold = sWinit[lane & 15];

    for (int it = 0; it < NITER; it++) {
        ull S[16];
#pragma unroll
        for (int m = 0; m < 16; m++) S[m] = 0ull;
#pragma unroll
        for (int p = 0; p < 8; p++) {
            ull x2 = P[p][0];
            ull A = W[14], B = W[15];
#pragma unroll
            for (int j = 6; j >= 1; j--) {
                A = fma2(A, x2, W[2 * j]);
                B = fma2(B, x2, W[2 * j + 1]);
            }
            A = fma2(A, x2, W[0]);
            B = fma2(B, x2, W[1]);
            ull H = fma2(X[p], B, A);
            float hlo, hhi; upk2(hlo, hhi, H);
            ull t = pk2(MUV * rcpa(hlo), MUV * rcpa(hhi));
            ull tx = mul2(t, X[p]);
            S[0] = add2(S[0], t);
            S[1] = add2(S[1], tx);
#pragma unroll
            for (int j = 1; j < 8; j++) {
                S[2 * j]     = fma2(t,  P[p][j - 1], S[2 * j]);
                S[2 * j + 1] = fma2(tx, P[p][j - 1], S[2 * j + 1]);
            }
        }
        float v[16];
#pragma unroll
        for (int m = 0; m < 16; m++) { float lo, hi; upk2(lo, hi, S[m]); v[m] = lo + hi; }
        float u8[8];
#pragma unroll
        for (int q = 0; q < 8; q++) {
            float keep = (lane & 1) ? v[2 * q + 1] : v[2 * q];
            float send = (lane & 1) ? v[2 * q] : v[2 * q + 1];
            u8[q] = keep + __shfl_xor_sync(0xffffffffu, send, 1);
        }
        float u4[4];
#pragma unroll
        for (int q = 0; q < 4; q++) {
            float keep = (lane & 2) ? u8[2 * q + 1] : u8[2 * q];
            float send = (lane & 2) ? u8[2 * q] : u8[2 * q + 1];
            u4[q] = keep + __shfl_xor_sync(0xffffffffu, send, 2);
        }
        float u2v[2];
#pragma unroll
        for (int q = 0; q < 2; q++) {
            float keep = (lane & 4) ? u4[2 * q + 1] : u4[2 * q];
            float send = (lane & 4) ? u4[2 * q] : u4[2 * q + 1];
            u2v[q] = keep + __shfl_xor_sync(0xffffffffu, send, 4);
        }
        float k1 = (lane & 8) ? u2v[1] : u2v[0];
        float s1 = (lane & 8) ? u2v[0] : u2v[1];
        float u1f = k1 + __shfl_xor_sync(0xffffffffu, s1, 8);
        float tot = u1f + __shfl_xor_sync(0xffffffffu, u1f, 16);
        int par = it & 1;
        if (lane < 16) sS[par][wid][lane] = tot;
        __syncthreads();
        int m = lane & 15;
        float a = 0.0f;
#pragma unroll
        for (int q = 0; q < 8; q++) a += sS[par][q][m];
        float nu = (m == 0) ? NU0 : MUV;
        float wv = nu * rcpa(a);
        float delta = fabsf(wv - wold) * rcpa(fmaxf(fabsf(wold), 1e-30f));
        wold = wv;
        float md = warp_max(delta);
#pragma unroll
        for (int m2 = 0; m2 < 16; m2++) {
            float x = __shfl_sync(0xffffffffu, wv, m2);
            W[m2] = pk2(x, x);
        }
        if (md < CONVTOL) break;
    }
    if (tid < 16) g_w[b * 16 + tid] = wold;
}

// ---------------- output: Gamma, A, norm — grid NB*8; last block writes sqrt ----------------
__global__ __launch_bounds__(256) void kOut(const float* __restrict__ scores,
                                            float* __restrict__ out, int out_size) {
    int blk = blockIdx.x;
    int b = blk >> 3, q = blk & 7;
    int tid = threadIdx.x, lane = tid & 31, wid = tid >> 5;
    __shared__ float sWs[16], sinv[KK];
    if (tid < 16) sWs[tid] = g_w[b * 16 + tid];
    if (tid < KK) sinv[tid] = 1.0f / g_colsum[b * KK + tid];
    __syncthreads();
    ull W[16];
#pragma unroll
    for (int m = 0; m < 16; m++) W[m] = pk2(sWs[m], sWs[m]);
    float c2 = g_P.c_exp2;
    const float2* sc2 = reinterpret_cast<const float2*>(scores + b * NN);
    float nacc = 0.0f;
    {
        int pairIdx = q * 256 + tid;   // 0..2047
        float2 s = sc2[pairIdx];
        float xlo = exp2f(c2 * fixs(s.x));
        float xhi = exp2f(c2 * fixs(s.y));
        ull x = pk2(xlo, xhi);
        ull x2 = mul2(x, x);
        ull P[7];
        P[0] = x2;
#pragma unroll
        for (int j = 1; j < 7; j++) P[j] = mul2(P[j - 1], x2);
        ull A = W[14], B = W[15];
#pragma unroll
        for (int j = 6; j >= 1; j--) {
            A = fma2(A, x2, W[2 * j]);
            B = fma2(B, x2, W[2 * j + 1]);
        }
        A = fma2(A, x2, W[0]);
        B = fma2(B, x2, W[1]);
        ull H = fma2(x, B, A);
        float hlo, hhi; upk2(hlo, hhi, H);
        ull t = pk2(MUV * rcpa(hlo), MUV * rcpa(hhi));
        ull tx = mul2(t, x);

        int e0 = 2 * pairIdx;
        float* Ao0 = out + ((size_t)(b * NN + e0)) * 15;
        float* Ao1 = Ao0 + 15;
        float racc0 = 0.0f, racc1 = 0.0f;
        float g0lo = 0.0f, g0hi = 0.0f;
#pragma unroll
        for (int m = 0; m < 16; m++) {
            ull base;
            if (m == 0) base = t;
            else if (m == 1) base = tx;
            else if ((m & 1) == 0) base = mul2(t, P[m / 2 - 1]);
            else base = mul2(tx, P[(m - 1) / 2 - 1]);
            ull g = mul2(base, W[m]);
            float glo, ghi; upk2(glo, ghi, g);
            if (m == 0) { g0lo = glo; g0hi = ghi; }
            else {
                int c = 15 - m;
                Ao0[c] = 4096.0f * glo;
                Ao1[c] = 4096.0f * ghi;
                const float2 sg2 = *reinterpret_cast<const float2*>(
                    &g_sig[(b * KK + c) * NN + e0]);
                float sn0 = sg2.x * sinv[c];
                float sn1 = sg2.y * sinv[c];
                racc0 += sn0; racc1 += sn1;
                float d0 = glo - sn0 * MUV;
                float d1 = ghi - sn1 * MUV;
                nacc += d0 * d0 + d1 * d1;
            }
        }
        float l0 = fminf(fmaxf((1.0f - racc0) * MUV, SMALLV), 1.0f - SMALLV);
        float l1 = fminf(fmaxf((1.0f - racc1) * MUV, SMALLV), 1.0f - SMALLV);
        float d0 = g0lo - l0, d1 = g0hi - l1;
        nacc += d0 * d0 + d1 * d1;
    }
    nacc = warp_sum(nacc);
    __shared__ float snrm[8];
    if (!lane) snrm[wid] = nacc;
    __syncthreads();
    if (tid == 0) {
        float a = 0.0f;
        for (int w = 0; w < 8; w++) a += snrm[w];
        atomicAdd(&g_norm, (double)a);
        __threadfence();
        unsigned tkt = atomicAdd(&g_cnt, 1u);
        if (tkt == gridDim.x - 1) {
            double nv = atomicAdd(&g_norm, 0.0);
            out[out_size - 1] = sqrtf((float)nv);
            g_cnt = 0;   // reset for next graph replay
        }
    }
}

extern "C" void kernel_launch(void* const* d_in, const int* in_sizes, int n_in,
                              void* d_out, int out_size) {
    const float* scores = (const float*)d_in[0];
    const float* tau    = (const float*)d_in[1];
    const float* w1     = (const float*)d_in[2];
    float* out = (float*)d_out;
    kPre0<<<2 * NB, 512>>>(scores, tau, w1);
    kB<<<NB * 8, 256>>>(scores);
    kC<<<NB * 8, 256>>>(scores, w1);
    kMain<<<NB, 256>>>(scores, w1);
    kOut<<<NB * 8, 256>>>(scores, out, out_size);
}

// round 16
// speedup vs baseline: 1.2145x; 1.2145x over previous
#include <cuda_runtime.h>
#include <math.h>

#define NB 128
#define NN 4096
#define KK 15
#define EPSV 0.1f
#define SMALLV 1e-20f
#define MUV 2.44140625e-4f   /* 1/4096 */
#define NU0 (4081.0f/4096.0f)
#define NITER 200
#define CONVTOL 1e-6f
#define LOG2E 1.4426950408889634f

typedef unsigned long long ull;

// ---------------- minimal global scratch ----------------
__device__ float g_mx[NB], g_mn[NB];
__device__ int   g_fl[NB];
__device__ double g_norm;
__device__ unsigned g_cnt;      // norm ticket (self-reset)
__device__ unsigned g_barcnt;   // grid barrier count (self-reset)
__device__ unsigned g_bargen;   // grid barrier generation (monotonic)

// ---------------- helpers ----------------
__device__ __forceinline__ float warp_sum(float v) {
#pragma unroll
    for (int o = 16; o > 0; o >>= 1) v += __shfl_xor_sync(0xffffffffu, v, o);
    return v;
}
__device__ __forceinline__ float warp_max(float v) {
#pragma unroll
    for (int o = 16; o > 0; o >>= 1) v = fmaxf(v, __shfl_xor_sync(0xffffffffu, v, o));
    return v;
}
__device__ __forceinline__ float warp_min(float v) {
#pragma unroll
    for (int o = 16; o > 0; o >>= 1) v = fminf(v, __shfl_xor_sync(0xffffffffu, v, o));
    return v;
}
__device__ __forceinline__ int warp_or(int v) {
#pragma unroll
    for (int o = 16; o > 0; o >>= 1) v |= __shfl_xor_sync(0xffffffffu, v, o);
    return v;
}
__device__ __forceinline__ float rcpa(float x) {
    float y; asm("rcp.approx.f32 %0, %1;" : "=f"(y) : "f"(x)); return y;
}
__device__ __forceinline__ float fixinf(float s) {
    return (isinf(s) && s < 0.0f) ? -3.4e38f : s;
}

// ---------------- packed f32x2 (sm_103a) ----------------
__device__ __forceinline__ ull pk2(float lo, float hi) {
    ull r; asm("mov.b64 %0, {%1,%2};" : "=l"(r) : "f"(lo), "f"(hi)); return r;
}
__device__ __forceinline__ void upk2(float& lo, float& hi, ull v) {
    asm("mov.b64 {%0,%1}, %2;" : "=f"(lo), "=f"(hi) : "l"(v));
}
__device__ __forceinline__ ull fma2(ull a, ull b, ull c) {
    ull d; asm("fma.rn.f32x2 %0, %1, %2, %3;" : "=l"(d) : "l"(a), "l"(b), "l"(c)); return d;
}
__device__ __forceinline__ ull mul2(ull a, ull b) {
    ull d; asm("mul.rn.f32x2 %0, %1, %2;" : "=l"(d) : "l"(a), "l"(b)); return d;
}
__device__ __forceinline__ ull add2(ull a, ull b) {
    ull d; asm("add.rn.f32x2 %0, %1, %2;" : "=l"(d) : "l"(a), "l"(b)); return d;
}

// sense-reversing grid barrier: all 128 CTAs are co-resident (1/SM), safe.
__device__ __forceinline__ void gridbar() {
    __syncthreads();
    if (threadIdx.x == 0) {
        __threadfence();
        unsigned gen = atomicAdd(&g_bargen, 0u);
        unsigned t = atomicAdd(&g_barcnt, 1u);
        if (t == gridDim.x - 1) {
            g_barcnt = 0u;
            __threadfence();
            atomicAdd(&g_bargen, 1u);
        } else {
            while (atomicAdd(&g_bargen, 0u) == gen) { __nanosleep(64); }
        }
    }
    __syncthreads();
}

// ==================== the whole pipeline in ONE kernel ====================
__global__ __launch_bounds__(512) void kAll(const float* __restrict__ scores,
                                            const float* __restrict__ tau,
                                            const float* __restrict__ w1,
                                            float* __restrict__ out, int out_size) {
    int b = blockIdx.x, tid = threadIdx.x, lane = tid & 31, wid = tid >> 5; // 16 warps
    __shared__ float ss[NN];         // row scores (raw, then fixed)
    __shared__ float sE[NN];         // exp2(s * itau2)
    __shared__ float stv[KK];
    __shared__ float sEj[KK], srEj[KK], sinv[KK], scol[KK], slc[KK], scb[KK], sgg[KK];
    __shared__ float smx[16], smn[16]; __shared__ int sfl[16];
    __shared__ float swm[16];
    __shared__ float sbc; __shared__ int claim;
    __shared__ float sred[16][16];   // 16-warp x 15-col reduction scratch
    __shared__ float sy16[16][5];
    __shared__ float ss1[16], ss2[16];
    __shared__ float sS[2][16][16];
    __shared__ float sPar[8];        // filled,invC,alpha,itau2,capA,epst,c2,SL
    __shared__ float yf[5], sWinit[16];

    // ---- phase A: load row once; minmax partials; top-15 ----
    const float4* p4 = reinterpret_cast<const float4*>(scores + b * NN) + tid * 2;
    float4 a4 = p4[0], b4 = p4[1];
    reinterpret_cast<float4*>(ss)[tid * 2] = a4;
    reinterpret_cast<float4*>(ss)[tid * 2 + 1] = b4;
    float v[8] = {a4.x, a4.y, a4.z, a4.w, b4.x, b4.y, b4.z, b4.w};
    {
        float mx = -3.4e38f, mn = 3.4e38f; int fl = 0;
#pragma unroll
        for (int t = 0; t < 8; t++) {
            float x = v[t];
            if (isinf(x) && x < 0.0f) fl = 1;
            else mn = fminf(mn, x);
            mx = fmaxf(mx, x);
        }
        mx = warp_max(mx); mn = warp_min(mn); fl = warp_or(fl);
        if (!lane) { smx[wid] = mx; smn[wid] = mn; sfl[wid] = fl; }
        __syncthreads();
        if (tid == 0) {
            for (int w = 1; w < 16; w++) { mx = fmaxf(mx, smx[w]); mn = fminf(mn, smn[w]); fl |= sfl[w]; }
            g_mx[b] = mx; g_mn[b] = mn; g_fl[b] = fl;
            if (b == 0) g_norm = 0.0;
        }
    }
    // top-15 via 15 masked argmax rounds (sentinel for -inf)
#pragma unroll
    for (int e = 0; e < 8; e++) v[e] = fixinf(v[e]);
    for (int r = 0; r < KK; r++) {
        float lm = v[0];
#pragma unroll
        for (int e = 1; e < 8; e++) lm = fmaxf(lm, v[e]);
        lm = warp_max(lm);
        if (!lane) swm[wid] = lm;
        __syncthreads();
        if (tid == 0) {
            float m = swm[0];
            for (int w = 1; w < 16; w++) m = fmaxf(m, swm[w]);
            sbc = m; claim = 0;
            stv[r] = m;
        }
        __syncthreads();
        float m = sbc;
        int idx = -1;
#pragma unroll
        for (int e = 0; e < 8; e++) if (idx < 0 && v[e] == m) idx = e;
        if (idx >= 0) {
            int old = atomicAdd(&claim, 1);
            if (old == 0) v[idx] = -3.4e38f;
        }
    }

    // ---- the single grid barrier: minmax partials now globally visible ----
    gridbar();

    // ---- phase C: every CTA computes global params redundantly ----
    if (tid < 128) {
        float mx = g_mx[tid], mn = g_mn[tid]; int fl = g_fl[tid];
        mx = warp_max(mx); mn = warp_min(mn); fl = warp_or(fl);
        if (!lane) { smx[wid] = mx; smn[wid] = mn; sfl[wid] = fl; }
    }
    __syncthreads();
    if (tid == 0) {
        float mx = smx[0], mn = smn[0]; int fl = sfl[0];
        for (int w = 1; w < 4; w++) { mx = fmaxf(mx, smx[w]); mn = fminf(mn, smn[w]); fl |= sfl[w]; }
        float filled = mn - (mx - mn);
        float lo = fl ? filled : mn;
        float d1 = lo - 15.0f, d2 = mx - 15.0f;
        float Cmax = fmaxf(fmaxf(lo * lo, d1 * d1), fmaxf(mx * mx, d2 * d2));
        float invC = 1.0f / Cmax;
        float itau = 1.0f / tau[0];
        sPar[0] = filled; sPar[1] = invC; sPar[2] = 10.0f * invC;
        sPar[3] = itau * LOG2E;
        sPar[4] = 46.0517362f / itau;
        sPar[5] = EPSV * itau;
        sPar[6] = 2.0f * (10.0f * invC) * LOG2E;
    }
    __syncthreads();
    float filled = sPar[0], invC = sPar[1], alpha = sPar[2], itau2 = sPar[3];
    float capA = sPar[4], epst = sPar[5], c2 = sPar[6];

    // fix ss in place + build sE table
#pragma unroll
    for (int e = 0; e < 8; e++) {
        int i = tid + e * 512;
        float s = ss[i];
        if (isinf(s) && s < 0.0f) s = filled;
        ss[i] = s;
        sE[i] = exp2f(s * itau2);
    }
    if (tid < KK) {
        float E = exp2f(stv[tid] * itau2);
        sEj[tid] = E;
        srEj[tid] = 1.0f / E;
    }
    __syncthreads();

    // ---- phase D: column sums of sigma ----
    {
        float cs[KK];
#pragma unroll
        for (int j = 0; j < KK; j++) cs[j] = 0.0f;
#pragma unroll
        for (int e = 0; e < 8; e++) {
            int i = tid + e * 512;
            float E = sE[i];
            float rE = rcpa(E);
#pragma unroll
            for (int j = 0; j < KK; j++) {
                float sg = rcpa(1.0f + fmaxf(sEj[j] * rE, E * srEj[j])) + SMALLV;
                cs[j] += sg;
            }
        }
#pragma unroll
        for (int j = 0; j < KK; j++) cs[j] = warp_sum(cs[j]);
        if (!lane) {
#pragma unroll
            for (int j = 0; j < KK; j++) sred[wid][j] = cs[j];
        }
        __syncthreads();
        if (tid < KK) {
            float a = 0.0f;
            for (int w = 0; w < 16; w++) a += sred[w][tid];
            scol[tid] = a;
            sinv[tid] = 1.0f / a;
            slc[tid] = EPSV * __logf(4096.0f * a);
        }
        __syncthreads();
        if (tid == 0) {
            float a = 0.0f;
            for (int c = 0; c < KK; c++) a += slc[c];
            sPar[7] = a;
        }
        __syncthreads();
    }
    float SL = sPar[7];

    // ---- phase E: rank-5 warm start (analytic log-sigmoid) ----
    {
        float y[5] = {0, 0, 0, 0, 0};
        float colA[KK];
#pragma unroll
        for (int c = 0; c < KK; c++) colA[c] = 0.0f;
        float ssum = 0.0f, ssum2 = 0.0f;
#pragma unroll
        for (int e = 0; e < 8; e++) {
            int i = tid + e * 512;
            float s = ss[i];
            float E = sE[i];
            float rE = rcpa(E);
            float rowacc = 0.0f, rowA = 0.0f, rowSg = 0.0f;
#pragma unroll
            for (int c = 0; c < KK; c++) {
                float sg = rcpa(1.0f + fmaxf(sEj[c] * rE, E * srEj[c])) + SMALLV;
                rowacc += sg * sinv[c];
                rowSg += sg;
                float ad = fminf(fabsf(stv[c] - s), capA);
                rowA += ad;
                colA[c] += ad;
            }
            ssum += s; ssum2 += s * s;
            float last = fminf(fmaxf((1.0f - rowacc) * MUV, SMALLV), 1.0f - SMALLV);
            float lnl = __logf(last);
            float R = (16.0f * s * s - 240.0f * s + 1240.0f) * invC
                    - epst * rowA - EPSV * rowSg + EPSV * lnl - SL;
            const float* wr = w1 + (size_t)i * 5;
#pragma unroll
            for (int r = 0; r < 5; r++) y[r] += R * wr[r];
        }
#pragma unroll
        for (int r = 0; r < 5; r++) y[r] = warp_sum(y[r]);
#pragma unroll
        for (int c = 0; c < KK; c++) colA[c] = warp_sum(colA[c]);
        ssum = warp_sum(ssum);
        ssum2 = warp_sum(ssum2);
        if (!lane) {
#pragma unroll
            for (int r = 0; r < 5; r++) sy16[wid][r] = y[r];
#pragma unroll
            for (int c = 0; c < KK; c++) sred[wid][c] = colA[c];
            ss1[wid] = ssum; ss2[wid] = ssum2;
        }
        __syncthreads();
        if (tid < KK) {
            int c = tid;
            float ca = 0.0f, S1 = 0.0f, S2 = 0.0f;
            for (int w = 0; w < 16; w++) { ca += sred[w][c]; S1 += ss1[w]; S2 += ss2[w]; }
            float a = (float)(KK - c);
            scb[c] = (S2 - 2.0f * a * S1 + 4096.0f * a * a) * invC
                   - epst * ca - EPSV * scol[c] - 4096.0f * slc[c];
        }
        __syncthreads();
        if (tid < 5) {
            float a = 0.0f;
            for (int w = 0; w < 16; w++) a += sy16[w][tid];
            for (int c = 0; c < KK; c++) a += scb[c] * w1[(size_t)(NN + c) * 5 + tid];
            yf[tid] = a;
        }
        __syncthreads();
        if (tid < KK) {
            float g = 0.0f;
#pragma unroll
            for (int r = 0; r < 5; r++) g += yf[r] * w1[(size_t)(NN + tid) * 5 + r];
            sgg[tid] = g;
        }
        __syncthreads();
        if (tid < 16) {
            sWinit[tid] = (tid == 0) ? 1.0f
                : __expf(10.0f * sgg[KK - tid] - alpha * (float)(tid * tid));
        }
        __syncthreads();
    }

    // ---- phase F: Sinkhorn loop (512 threads, 4 pairs/thread, early exit) ----
    ull X[4], X2[4], X4[4], X8[4];
    const float2* ssp2 = reinterpret_cast<const float2*>(ss);
#pragma unroll
    for (int p = 0; p < 4; p++) {
        float2 sv = ssp2[tid + p * 512];
        ull x = pk2(exp2f(c2 * sv.x), exp2f(c2 * sv.y));
        X[p] = x;
        X2[p] = mul2(x, x);
        X4[p] = mul2(X2[p], X2[p]);
        X8[p] = mul2(X4[p], X4[p]);
    }
    ull W[16];
#pragma unroll
    for (int m = 0; m < 16; m++) { float w = sWinit[m]; W[m] = pk2(w, w); }
    float wold = sWinit[lane & 15];

    for (int it = 0; it < NITER; it++) {
        ull S[16];
#pragma unroll
        for (int m = 0; m < 16; m++) S[m] = 0ull;
#pragma unroll
        for (int p = 0; p < 4; p++) {
            ull x2 = X2[p];
            ull A = W[14], B = W[15];
#pragma unroll
            for (int j = 6; j >= 1; j--) {
                A = fma2(A, x2, W[2 * j]);
                B = fma2(B, x2, W[2 * j + 1]);
            }
            A = fma2(A, x2, W[0]);
            B = fma2(B, x2, W[1]);
            ull H = fma2(X[p], B, A);
            float hlo, hhi; upk2(hlo, hhi, H);
            ull t0 = pk2(MUV * rcpa(hlo), MUV * rcpa(hhi));
            ull t1 = mul2(t0, X[p]);
            ull t2 = mul2(t0, x2);
            ull t3 = mul2(t1, x2);
            ull u0 = mul2(t0, X4[p]);
            ull u1 = mul2(t1, X4[p]);
            ull u2 = mul2(t2, X4[p]);
            ull u3 = mul2(t3, X4[p]);
            S[0] = add2(S[0], t0);  S[1] = add2(S[1], t1);
            S[2] = add2(S[2], t2);  S[3] = add2(S[3], t3);
            S[4] = add2(S[4], u0);  S[5] = add2(S[5], u1);
            S[6] = add2(S[6], u2);  S[7] = add2(S[7], u3);
            S[8]  = fma2(t0, X8[p], S[8]);
            S[9]  = fma2(t1, X8[p], S[9]);
            S[10] = fma2(t2, X8[p], S[10]);
            S[11] = fma2(t3, X8[p], S[11]);
            S[12] = fma2(u0, X8[p], S[12]);
            S[13] = fma2(u1, X8[p], S[13]);
            S[14] = fma2(u2, X8[p], S[14]);
            S[15] = fma2(u3, X8[p], S[15]);
        }
        float vv[16];
#pragma unroll
        for (int m = 0; m < 16; m++) { float lo, hi; upk2(lo, hi, S[m]); vv[m] = lo + hi; }
        float u8[8];
#pragma unroll
        for (int q = 0; q < 8; q++) {
            float keep = (lane & 1) ? vv[2 * q + 1] : vv[2 * q];
            float send = (lane & 1) ? vv[2 * q] : vv[2 * q + 1];
            u8[q] = keep + __shfl_xor_sync(0xffffffffu, send, 1);
        }
        float u4[4];
#pragma unroll
        for (int q = 0; q < 4; q++) {
            float keep = (lane & 2) ? u8[2 * q + 1] : u8[2 * q];
            float send = (lane & 2) ? u8[2 * q] : u8[2 * q + 1];
            u4[q] = keep + __shfl_xor_sync(0xffffffffu, send, 2);
        }
        float u2v[2];
#pragma unroll
        for (int q = 0; q < 2; q++) {
            float keep = (lane & 4) ? u4[2 * q + 1] : u4[2 * q];
            float send = (lane & 4) ? u4[2 * q] : u4[2 * q + 1];
            u2v[q] = keep + __shfl_xor_sync(0xffffffffu, send, 4);
        }
        float k1 = (lane & 8) ? u2v[1] : u2v[0];
        float s1 = (lane & 8) ? u2v[0] : u2v[1];
        float u1f = k1 + __shfl_xor_sync(0xffffffffu, s1, 8);
        float tot = u1f + __shfl_xor_sync(0xffffffffu, u1f, 16);
        int par = it & 1;
        if (lane < 16) sS[par][wid][lane] = tot;
        __syncthreads();
        int m = lane & 15;
        float a = 0.0f;
#pragma unroll
        for (int q = 0; q < 16; q++) a += sS[par][q][m];
        float nu = (m == 0) ? NU0 : MUV;
        float wv = nu * rcpa(a);
        float delta = fabsf(wv - wold) * rcpa(fmaxf(fabsf(wold), 1e-30f));
        wold = wv;
        float md = warp_max(delta);
#pragma unroll
        for (int m2 = 0; m2 < 16; m2++) {
            float x = __shfl_sync(0xffffffffu, wv, m2);
            W[m2] = pk2(x, x);
        }
        if (md < CONVTOL) break;
    }

    // ---- phase G: Gamma, output A, norm ----
    float nacc = 0.0f;
#pragma unroll
    for (int p = 0; p < 4; p++) {
        ull x2 = X2[p];
        ull A = W[14], B = W[15];
#pragma unroll
        for (int j = 6; j >= 1; j--) {
            A = fma2(A, x2, W[2 * j]);
            B = fma2(B, x2, W[2 * j + 1]);
        }
        A = fma2(A, x2, W[0]);
        B = fma2(B, x2, W[1]);
        ull H = fma2(X[p], B, A);
        float hlo, hhi; upk2(hlo, hhi, H);
        ull t0 = pk2(MUV * rcpa(hlo), MUV * rcpa(hhi));
        ull t1 = mul2(t0, X[p]);
        ull t2 = mul2(t0, X2[p]);
        ull t3 = mul2(t1, X2[p]);
        ull u0 = mul2(t0, X4[p]);
        ull u1 = mul2(t1, X4[p]);
        ull u2 = mul2(t2, X4[p]);
        ull u3 = mul2(t3, X4[p]);
        int pairIdx = tid + p * 512;
        int e0 = 2 * pairIdx;
        float E0 = sE[e0], E1 = sE[e0 + 1];
        float rE0 = rcpa(E0), rE1 = rcpa(E1);
        float* Ao0 = out + ((size_t)(b * NN + e0)) * 15;
        float* Ao1 = Ao0 + 15;
        float racc0 = 0.0f, racc1 = 0.0f;
        float g0lo = 0.0f, g0hi = 0.0f;
#pragma unroll
        for (int m = 0; m < 16; m++) {
            ull base;
            if (m == 0) base = t0; else if (m == 1) base = t1;
            else if (m == 2) base = t2; else if (m == 3) base = t3;
            else if (m == 4) base = u0; else if (m == 5) base = u1;
            else if (m == 6) base = u2; else if (m == 7) base = u3;
            else if (m == 8)  base = mul2(t0, X8[p]);
            else if (m == 9)  base = mul2(t1, X8[p]);
            else if (m == 10) base = mul2(t2, X8[p]);
            else if (m == 11) base = mul2(t3, X8[p]);
            else if (m == 12) base = mul2(u0, X8[p]);
            else if (m == 13) base = mul2(u1, X8[p]);
            else              base = mul2(u2, X8[p]);
            if (m == 15) base = mul2(u3, X8[p]);
            ull g = mul2(base, W[m]);
            float glo, ghi; upk2(glo, ghi, g);
            if (m == 0) { g0lo = glo; g0hi = ghi; }
            else {
                int c = 15 - m;
                Ao0[c] = 4096.0f * glo;
                Ao1[c] = 4096.0f * ghi;
                float sg0 = rcpa(1.0f + fmaxf(sEj[c] * rE0, E0 * srEj[c])) + SMALLV;
                float sg1 = rcpa(1.0f + fmaxf(sEj[c] * rE1, E1 * srEj[c])) + SMALLV;
                float sn0 = sg0 * sinv[c];
                float sn1 = sg1 * sinv[c];
                racc0 += sn0; racc1 += sn1;
                float d0 = glo - sn0 * MUV;
                float d1 = ghi - sn1 * MUV;
                nacc += d0 * d0 + d1 * d1;
            }
        }
        float l0 = fminf(fmaxf((1.0f - racc0) * MUV, SMALLV), 1.0f - SMALLV);
        float l1 = fminf(fmaxf((1.0f - racc1) * MUV, SMALLV), 1.0f - SMALLV);
        float d0 = g0lo - l0, d1 = g0hi - l1;
        nacc += d0 * d0 + d1 * d1;
    }
    nacc = warp_sum(nacc);
    if (!lane) ss1[wid] = nacc;
    __syncthreads();
    if (tid == 0) {
        float a = 0.0f;
        for (int w = 0; w < 16; w++) a += ss1[w];
        atomicAdd(&g_norm, (double)a);
        __threadfence();
        unsigned tkt = atomicAdd(&g_cnt, 1u);
        if (tkt == gridDim.x - 1) {
            double nv = atomicAdd(&g_norm, 0.0);
            out[out_size - 1] = sqrtf((float)nv);
            g_cnt = 0u;   // reset for next graph replay
        }
    }
}

extern "C" void kernel_launch(void* const* d_in, const int* in_sizes, int n_in,
                              void* d_out, int out_size) {
    const float* scores = (const float*)d_in[0];
    const float* tau    = (const float*)d_in[1];
    const float* w1     = (const float*)d_in[2];
    float* out = (float*)d_out;
    kAll<<<NB, 512>>>(scores, tau, w1, out, out_size);
}